// round 15
// baseline (speedup 1.0000x reference)
#include <cuda_runtime.h>
#include <cuda_bf16.h>
#include <stdint.h>
#include <string.h>

// ---------------- problem shape (fixed) ----------------
#define T_TOK 16384
#define D_HID 4096
#define E_EXP 256
#define TOPK  8

#define BM 32
#define BN 128
#define NKC (D_HID / 16)        // 256 k16 chunks
#define PRE 4                   // B pipeline stages (power of 2)

#define B_STG 8192              // 512 x uint4 (128 experts * 4 lanegroups)
#define SMEM_TOTAL (PRE * B_STG) // 32768 -> 6 CTAs/SM = 196608

// W packed fragment-order: idx = kc*1024 + n*4 + l4
// uint4 = { hi(k0,k1), hi(k8,k9), lo(k0,k1), lo(k8,k9) }, k = kc*16 + l4*2 (+8)
__device__ uint4 g_Wp[NKC * E_EXP * 4];

// ---------------- helpers ----------------
__device__ __forceinline__ uint32_t smem_u32(const void* p) {
    uint32_t a;
    asm("{ .reg .u64 t; cvta.to.shared.u64 t, %1; cvt.u32.u64 %0, t; }" : "=r"(a) : "l"(p));
    return a;
}
__device__ __forceinline__ void cp16(void* dst_smem, const void* src_gmem) {
    uint32_t d = smem_u32(dst_smem);
    asm volatile("cp.async.cg.shared.global [%0], [%1], 16;" :: "r"(d), "l"(src_gmem) : "memory");
}
#define CP_COMMIT()  asm volatile("cp.async.commit_group;" ::: "memory")
#define CP_WAIT2()   asm volatile("cp.async.wait_group 2;" ::: "memory")

__device__ __forceinline__ void mma16816(float* c, const uint32_t* a, uint32_t b0, uint32_t b1) {
    asm volatile(
        "mma.sync.aligned.m16n8k16.row.col.f32.bf16.bf16.f32 "
        "{%0,%1,%2,%3}, {%4,%5,%6,%7}, {%8,%9}, {%0,%1,%2,%3};"
        : "+f"(c[0]), "+f"(c[1]), "+f"(c[2]), "+f"(c[3])
        : "r"(a[0]), "r"(a[1]), "r"(a[2]), "r"(a[3]), "r"(b0), "r"(b1));
}

__device__ __forceinline__ void split2(float f0, float f1, uint32_t& h, uint32_t& l) {
    __nv_bfloat162 hb = __floats2bfloat162_rn(f0, f1);
    uint32_t hu; memcpy(&hu, &hb, 4);
    float g0 = __uint_as_float(hu << 16);
    float g1 = __uint_as_float(hu & 0xffff0000u);
    __nv_bfloat162 lb = __floats2bfloat162_rn(f0 - g0, f1 - g1);
    uint32_t lu; memcpy(&lu, &lb, 4);
    h = hu; l = lu;
}

// ---------------- kernel 1: pack W into fragment order (hi/lo) -------------
__global__ void cvt_w_kernel(const float* __restrict__ W) {
    int t = blockIdx.x * blockDim.x + threadIdx.x;
    int l4 = t & 3;
    int n  = (t >> 2) & 255;
    int kc = t >> 10;
    const float* p = W + (size_t)n * D_HID + kc * 16 + l4 * 2;
    float2 x = *(const float2*)p;
    float2 y = *(const float2*)(p + 8);
    uint4 o;
    split2(x.x, x.y, o.x, o.z);
    split2(y.x, y.y, o.y, o.w);
    g_Wp[t] = o;
}

// ---------------- kernel 2: HMMA bf16x3 GEMM, A via LDG prefetch, 6 CTA/SM -
__global__ void __launch_bounds__(128, 6)
gemm_kernel(const float* __restrict__ A, float* __restrict__ outS) {
    extern __shared__ char smem[];
    const int tid  = threadIdx.x;
    const int lane = tid & 31;
    const int warp = tid >> 5;           // 0..3
    const int wm   = warp >> 1;          // 0..1  (rows wm*16)
    const int wn   = warp & 1;           // 0..1  (cols wn*64)
    const int m0   = blockIdx.y * BM;    // n-tile fastest -> A L2 reuse
    const int n0   = blockIdx.x * BN;
    const int r    = lane >> 2;          // 0..7
    const int t4   = lane & 3;           // 0..3
    const int c2   = t4 * 2;             // 0,2,4,6

    // cp.async B: 512 uint4/stage; thread copies elems tid, tid+128, +256, +384
    const uint4* gB = g_Wp + (size_t)n0 * 4 + tid;
    char* bDst = smem + tid * 16;
    // A global fragment base: row = m0 + wm*16 + r, col c2 (+8 col, +8 row)
    const float* aBase = A + (size_t)(m0 + wm * 16 + r) * D_HID + c2;

    // LDS base for B
    char* bLds = smem + ((wn * 64 + r) * 4 + t4) * 16;

    float acc[8][4];
    #pragma unroll
    for (int f = 0; f < 8; ++f)
        #pragma unroll
        for (int q = 0; q < 4; ++q) acc[f][q] = 0.f;

    // prologue: B stages 0..PRE-2 (3 commits); A chunk 0 into registers
    #pragma unroll
    for (int s = 0; s < PRE - 1; ++s) {
        int so = s * B_STG;
        #pragma unroll
        for (int j = 0; j < 4; ++j)
            cp16(bDst + so + j * 2048, gB + (size_t)s * 1024 + j * 128);
        CP_COMMIT();
    }
    float2 raw01 = *(const float2*)(aBase);                    // (r,   c0..1)
    float2 raw23 = *(const float2*)(aBase + 8 * D_HID);        // (r+8, c0..1)
    float2 raw45 = *(const float2*)(aBase + 8);                // (r,   c8..9)
    float2 raw67 = *(const float2*)(aBase + 8 * D_HID + 8);    // (r+8, c8..9)

    for (int kc = 0; kc < NKC; ++kc) {
        CP_WAIT2();
        __syncthreads();

        int kn = kc + PRE - 1;
        if (kn < NKC) {
            int so = (kn & (PRE - 1)) * B_STG;
            #pragma unroll
            for (int j = 0; j < 4; ++j)
                cp16(bDst + so + j * 2048, gB + (size_t)kn * 1024 + j * 128);
        }
        CP_COMMIT();   // exactly one group per iteration

        // split current A raw -> bf16 hi/lo fragments (raw regs then die)
        uint32_t ah[4], al[4];
        split2(raw01.x, raw01.y, ah[0], al[0]);
        split2(raw23.x, raw23.y, ah[1], al[1]);
        split2(raw45.x, raw45.y, ah[2], al[2]);
        split2(raw67.x, raw67.y, ah[3], al[3]);

        // prefetch next A chunk (clamped at tail; redundant reload is harmless)
        {
            int knext = (kc + 1 < NKC) ? (kc + 1) : (NKC - 1);
            const float* ap = aBase + knext * 16;
            raw01 = *(const float2*)(ap);
            raw23 = *(const float2*)(ap + 8 * D_HID);
            raw45 = *(const float2*)(ap + 8);
            raw67 = *(const float2*)(ap + 8 * D_HID + 8);
        }

        const int so = (kc & (PRE - 1)) * B_STG;

        // B in groups of 2 n-frags (keeps live regs low)
        #pragma unroll
        for (int g = 0; g < 4; ++g) {
            uint4 b[2];
            #pragma unroll
            for (int j = 0; j < 2; ++j)
                b[j] = *(const uint4*)(bLds + so + (g * 2 + j) * 512);
            #pragma unroll
            for (int j = 0; j < 2; ++j) {
                float* c = acc[g * 2 + j];
                mma16816(c, ah, b[j].x, b[j].y);   // Ahi*Bhi
                mma16816(c, ah, b[j].z, b[j].w);   // Ahi*Blo
                mma16816(c, al, b[j].x, b[j].y);   // Alo*Bhi
            }
        }
    }

    // epilogue: warp writes 16x64
    int row0 = m0 + wm * 16 + r;
    float* po = outS + (size_t)row0 * E_EXP + n0 + wn * 64 + c2;
    #pragma unroll
    for (int f = 0; f < 8; ++f) {
        *(float2*)(po + f * 8)             = make_float2(acc[f][0], acc[f][1]);
        *(float2*)(po + 8 * E_EXP + f * 8) = make_float2(acc[f][2], acc[f][3]);
    }
}

// ---------------- kernel 3: softmax + bias top-8 router (1 warp/token) -----
__global__ void __launch_bounds__(256, 8)
router_kernel(const float* __restrict__ score, const float* __restrict__ bias,
              float* __restrict__ outW, float* __restrict__ outI) {
    const int lane = threadIdx.x & 31;
    const int warp = threadIdx.x >> 5;
    const int t = blockIdx.x * 8 + warp;

    float v[8], bj[8];
    #pragma unroll
    for (int j = 0; j < 8; ++j) {
        v[j]  = score[(size_t)t * E_EXP + lane + 32 * j];
        bj[j] = bias[lane + 32 * j];
    }
    float m = v[0];
    #pragma unroll
    for (int j = 1; j < 8; ++j) m = fmaxf(m, v[j]);
    #pragma unroll
    for (int o = 16; o > 0; o >>= 1) m = fmaxf(m, __shfl_xor_sync(0xFFFFFFFFu, m, o));
    float p[8], s = 0.f;
    #pragma unroll
    for (int j = 0; j < 8; ++j) { p[j] = expf(v[j] - m); s += p[j]; }
    #pragma unroll
    for (int o = 16; o > 0; o >>= 1) s += __shfl_xor_sync(0xFFFFFFFFu, s, o);
    float sc[8], biased[8];
    #pragma unroll
    for (int j = 0; j < 8; ++j) { sc[j] = p[j] / s; biased[j] = sc[j] + bj[j]; }

    unsigned picked = 0;
    #pragma unroll
    for (int rnk = 0; rnk < TOPK; ++rnk) {
        float bv = -__int_as_float(0x7f800000);
        int   bi = 0x7fffffff;
        float bu = 0.f;
        #pragma unroll
        for (int j = 0; j < 8; ++j) {
            if (!((picked >> j) & 1u)) {
                int idx = lane + 32 * j;
                float cv = biased[j];
                if (cv > bv || (cv == bv && idx < bi)) { bv = cv; bi = idx; bu = sc[j]; }
            }
        }
        #pragma unroll
        for (int o = 16; o > 0; o >>= 1) {
            float ov = __shfl_xor_sync(0xFFFFFFFFu, bv, o);
            int   oi = __shfl_xor_sync(0xFFFFFFFFu, bi, o);
            float ou = __shfl_xor_sync(0xFFFFFFFFu, bu, o);
            if (ov > bv || (ov == bv && oi < bi)) { bv = ov; bi = oi; bu = ou; }
        }
        if (lane == (bi & 31)) picked |= 1u << (bi >> 5);
        if (lane == rnk) {
            outW[(size_t)t * TOPK + rnk] = bu * 1.5f;
            outI[(size_t)t * TOPK + rnk] = (float)bi;
        }
    }
}

// ---------------- launch ----------------
extern "C" void kernel_launch(void* const* d_in, const int* in_sizes, int n_in,
                              void* d_out, int out_size) {
    (void)n_in; (void)in_sizes; (void)out_size;
    const float* A    = (const float*)d_in[0];
    const float* W    = (const float*)d_in[1];
    const float* bias = (const float*)d_in[2];
    float* out  = (float*)d_out;
    float* outS = out;
    float* outW = out + (size_t)T_TOK * E_EXP;
    float* outI = outW + (size_t)T_TOK * TOPK;

    cudaFuncSetAttribute(gemm_kernel, cudaFuncAttributeMaxDynamicSharedMemorySize, SMEM_TOTAL);

    cvt_w_kernel<<<(NKC * E_EXP * 4) / 256, 256>>>(W);
    dim3 grid(E_EXP / BN, T_TOK / BM);   // n fastest -> A reuse in L2
    gemm_kernel<<<grid, 128, SMEM_TOTAL>>>(A, outS);
    router_kernel<<<T_TOK / 8, 256>>>(outS, bias, outW, outI);
}

// round 16
// speedup vs baseline: 1.4734x; 1.4734x over previous
#include <cuda_runtime.h>
#include <cuda_bf16.h>
#include <stdint.h>
#include <string.h>

// ---------------- problem shape (fixed) ----------------
#define T_TOK 16384
#define D_HID 4096
#define E_EXP 256
#define TOPK  8

#define BM 32
#define BN 128
#define NKC (D_HID / 16)        // 256 k16 chunks
#define PRE 3                   // pipeline stages

#define A_PITCH 80              // 64B data + 16B pad
#define A_STG (BM * A_PITCH)    // 2560
#define B_STG 8192              // 512 x uint4 (128 experts * 4 lanegroups)
#define STG   (A_STG + B_STG)   // 10752
#define SMEM_TOTAL (PRE * STG)  // 32256 -> 6 CTAs/SM = 193536

// W packed fragment-order: idx = kc*1024 + n*4 + l4
// uint4 = { hi(k0,k1), hi(k8,k9), lo(k0,k1), lo(k8,k9) }, k = kc*16 + l4*2 (+8)
__device__ uint4 g_Wp[NKC * E_EXP * 4];

// ---------------- helpers ----------------
__device__ __forceinline__ uint32_t smem_u32(const void* p) {
    uint32_t a;
    asm("{ .reg .u64 t; cvta.to.shared.u64 t, %1; cvt.u32.u64 %0, t; }" : "=r"(a) : "l"(p));
    return a;
}
__device__ __forceinline__ void cp16(void* dst_smem, const void* src_gmem) {
    uint32_t d = smem_u32(dst_smem);
    asm volatile("cp.async.cg.shared.global [%0], [%1], 16;" :: "r"(d), "l"(src_gmem) : "memory");
}
#define CP_COMMIT()  asm volatile("cp.async.commit_group;" ::: "memory")
#define CP_WAIT1()   asm volatile("cp.async.wait_group 1;" ::: "memory")

__device__ __forceinline__ void mma16816(float* c, const uint32_t* a, uint32_t b0, uint32_t b1) {
    asm volatile(
        "mma.sync.aligned.m16n8k16.row.col.f32.bf16.bf16.f32 "
        "{%0,%1,%2,%3}, {%4,%5,%6,%7}, {%8,%9}, {%0,%1,%2,%3};"
        : "+f"(c[0]), "+f"(c[1]), "+f"(c[2]), "+f"(c[3])
        : "r"(a[0]), "r"(a[1]), "r"(a[2]), "r"(a[3]), "r"(b0), "r"(b1));
}

__device__ __forceinline__ void split2(float f0, float f1, uint32_t& h, uint32_t& l) {
    __nv_bfloat162 hb = __floats2bfloat162_rn(f0, f1);
    uint32_t hu; memcpy(&hu, &hb, 4);
    float g0 = __uint_as_float(hu << 16);
    float g1 = __uint_as_float(hu & 0xffff0000u);
    __nv_bfloat162 lb = __floats2bfloat162_rn(f0 - g0, f1 - g1);
    uint32_t lu; memcpy(&lu, &lb, 4);
    h = hu; l = lu;
}

// ---------------- kernel 1: pack W into fragment order (hi/lo) -------------
__global__ void cvt_w_kernel(const float* __restrict__ W) {
    int t = blockIdx.x * blockDim.x + threadIdx.x;
    int l4 = t & 3;
    int n  = (t >> 2) & 255;
    int kc = t >> 10;
    const float* p = W + (size_t)n * D_HID + kc * 16 + l4 * 2;
    float2 x = *(const float2*)p;
    float2 y = *(const float2*)(p + 8);
    uint4 o;
    split2(x.x, x.y, o.x, o.z);
    split2(y.x, y.y, o.y, o.w);
    g_Wp[t] = o;
}

// ---------------- kernel 2: HMMA bf16x3 GEMM, 32x128 CTA, 6 CTA/SM ---------
__global__ void __launch_bounds__(128, 6)
gemm_kernel(const float* __restrict__ A, float* __restrict__ outS) {
    extern __shared__ char smem[];
    const int tid  = threadIdx.x;
    const int lane = tid & 31;
    const int warp = tid >> 5;           // 0..3
    const int wm   = warp >> 1;          // 0..1  (rows wm*16)
    const int wn   = warp & 1;           // 0..1  (cols wn*64)
    const int m0   = blockIdx.y * BM;    // n-tile fastest -> A L2 reuse
    const int n0   = blockIdx.x * BN;
    const int r    = lane >> 2;          // 0..7
    const int t4   = lane & 3;           // 0..3
    const int c2   = t4 * 2;             // 0,2,4,6

    // cp.async A: 32 rows * 4 segs = 128 copies, one per thread
    const int a_row = tid >> 2, a_seg = tid & 3;
    const float* gA = A + (size_t)(m0 + a_row) * D_HID + a_seg * 4;
    char* aDst = smem + a_row * A_PITCH + a_seg * 16;
    // cp.async B: 512 uint4/stage; thread copies elems tid, tid+128, +256, +384
    const uint4* gB = g_Wp + (size_t)n0 * 4 + tid;
    char* bDst = smem + A_STG + tid * 16;

    // LDS bases (32-bit offsets)
    char* aLds = smem + (wm * 16 + r) * A_PITCH + c2 * 4;
    char* bLds = smem + A_STG + ((wn * 64 + r) * 4 + t4) * 16;

    float acc[8][4];
    #pragma unroll
    for (int f = 0; f < 8; ++f)
        #pragma unroll
        for (int q = 0; q < 4; ++q) acc[f][q] = 0.f;

    // prologue: stages 0..PRE-2 (2 commits)
    #pragma unroll
    for (int s = 0; s < PRE - 1; ++s) {
        int so = s * STG;
        cp16(aDst + so, gA + s * 16);
        #pragma unroll
        for (int j = 0; j < 4; ++j)
            cp16(bDst + so + j * 2048, gB + (size_t)s * 1024 + j * 128);
        CP_COMMIT();
    }

    int so_c = 0;                  // consume offset: stage kc % 3
    int so_p = (PRE - 1) * STG;    // produce offset: stage (kc+2) % 3

    for (int kc = 0; kc < NKC; ++kc) {
        CP_WAIT1();
        __syncthreads();

        int kn = kc + PRE - 1;
        if (kn < NKC) {
            cp16(aDst + so_p, gA + kn * 16);
            #pragma unroll
            for (int j = 0; j < 4; ++j)
                cp16(bDst + so_p + j * 2048, gB + (size_t)kn * 1024 + j * 128);
        }
        CP_COMMIT();   // exactly one group per iteration

        const int so = so_c;

        // A fragment (f32 from smem), split into bf16 hi/lo
        const char* ab = aLds + so;
        float2 f01 = *(const float2*)(ab);
        float2 f23 = *(const float2*)(ab + 8 * A_PITCH);
        float2 f45 = *(const float2*)(ab + 32);
        float2 f67 = *(const float2*)(ab + 8 * A_PITCH + 32);
        uint32_t ah[4], al[4];
        split2(f01.x, f01.y, ah[0], al[0]);
        split2(f23.x, f23.y, ah[1], al[1]);
        split2(f45.x, f45.y, ah[2], al[2]);
        split2(f67.x, f67.y, ah[3], al[3]);

        // B in groups of 2 n-frags (low live-reg pressure);
        // per acc element order: hi*bhi, hi*blo, lo*bhi (bit-identical)
        #pragma unroll
        for (int g = 0; g < 4; ++g) {
            uint4 b[2];
            #pragma unroll
            for (int j = 0; j < 2; ++j)
                b[j] = *(const uint4*)(bLds + so + (g * 2 + j) * 512);
            #pragma unroll
            for (int j = 0; j < 2; ++j) {
                float* c = acc[g * 2 + j];
                mma16816(c, ah, b[j].x, b[j].y);   // Ahi*Bhi
                mma16816(c, ah, b[j].z, b[j].w);   // Ahi*Blo
                mma16816(c, al, b[j].x, b[j].y);   // Alo*Bhi
            }
        }

        // advance ring offsets (wrap at 3 stages)
        so_c = (so_c == (PRE - 1) * STG) ? 0 : so_c + STG;
        so_p = (so_p == (PRE - 1) * STG) ? 0 : so_p + STG;
    }

    // epilogue: warp writes 16x64
    int row0 = m0 + wm * 16 + r;
    float* po = outS + (size_t)row0 * E_EXP + n0 + wn * 64 + c2;
    #pragma unroll
    for (int f = 0; f < 8; ++f) {
        *(float2*)(po + f * 8)             = make_float2(acc[f][0], acc[f][1]);
        *(float2*)(po + 8 * E_EXP + f * 8) = make_float2(acc[f][2], acc[f][3]);
    }
}

// ---------------- kernel 3: softmax + bias top-8 router (1 warp/token) -----
__global__ void __launch_bounds__(256, 8)
router_kernel(const float* __restrict__ score, const float* __restrict__ bias,
              float* __restrict__ outW, float* __restrict__ outI) {
    const int lane = threadIdx.x & 31;
    const int warp = threadIdx.x >> 5;
    const int t = blockIdx.x * 8 + warp;

    float v[8], bj[8];
    #pragma unroll
    for (int j = 0; j < 8; ++j) {
        v[j]  = score[(size_t)t * E_EXP + lane + 32 * j];
        bj[j] = bias[lane + 32 * j];
    }
    float m = v[0];
    #pragma unroll
    for (int j = 1; j < 8; ++j) m = fmaxf(m, v[j]);
    #pragma unroll
    for (int o = 16; o > 0; o >>= 1) m = fmaxf(m, __shfl_xor_sync(0xFFFFFFFFu, m, o));
    float p[8], s = 0.f;
    #pragma unroll
    for (int j = 0; j < 8; ++j) { p[j] = expf(v[j] - m); s += p[j]; }
    #pragma unroll
    for (int o = 16; o > 0; o >>= 1) s += __shfl_xor_sync(0xFFFFFFFFu, s, o);
    float sc[8], biased[8];
    #pragma unroll
    for (int j = 0; j < 8; ++j) { sc[j] = p[j] / s; biased[j] = sc[j] + bj[j]; }

    unsigned picked = 0;
    #pragma unroll
    for (int rnk = 0; rnk < TOPK; ++rnk) {
        float bv = -__int_as_float(0x7f800000);
        int   bi = 0x7fffffff;
        float bu = 0.f;
        #pragma unroll
        for (int j = 0; j < 8; ++j) {
            if (!((picked >> j) & 1u)) {
                int idx = lane + 32 * j;
                float cv = biased[j];
                if (cv > bv || (cv == bv && idx < bi)) { bv = cv; bi = idx; bu = sc[j]; }
            }
        }
        #pragma unroll
        for (int o = 16; o > 0; o >>= 1) {
            float ov = __shfl_xor_sync(0xFFFFFFFFu, bv, o);
            int   oi = __shfl_xor_sync(0xFFFFFFFFu, bi, o);
            float ou = __shfl_xor_sync(0xFFFFFFFFu, bu, o);
            if (ov > bv || (ov == bv && oi < bi)) { bv = ov; bi = oi; bu = ou; }
        }
        if (lane == (bi & 31)) picked |= 1u << (bi >> 5);
        if (lane == rnk) {
            outW[(size_t)t * TOPK + rnk] = bu * 1.5f;
            outI[(size_t)t * TOPK + rnk] = (float)bi;
        }
    }
}

// ---------------- launch ----------------
extern "C" void kernel_launch(void* const* d_in, const int* in_sizes, int n_in,
                              void* d_out, int out_size) {
    (void)n_in; (void)in_sizes; (void)out_size;
    const float* A    = (const float*)d_in[0];
    const float* W    = (const float*)d_in[1];
    const float* bias = (const float*)d_in[2];
    float* out  = (float*)d_out;
    float* outS = out;
    float* outW = out + (size_t)T_TOK * E_EXP;
    float* outI = outW + (size_t)T_TOK * TOPK;

    cudaFuncSetAttribute(gemm_kernel, cudaFuncAttributeMaxDynamicSharedMemorySize, SMEM_TOTAL);

    cvt_w_kernel<<<(NKC * E_EXP * 4) / 256, 256>>>(W);
    dim3 grid(E_EXP / BN, T_TOK / BM);   // n fastest -> A reuse in L2
    gemm_kernel<<<grid, 128, SMEM_TOTAL>>>(A, outS);
    router_kernel<<<T_TOK / 8, 256>>>(outS, bias, outW, outI);
}